// round 15
// baseline (speedup 1.0000x reference)
#include <cuda_runtime.h>
#include <cuda_fp16.h>
#include <cstdint>

// ---------------- problem constants ----------------
// B=16, H=W=64, C=512, NH=16, hd=32, WS=8, N=64, SS=4

// ---------------- device scratch ----------------
__device__ __half g_xh[33554432];              // fp16 query (pre-rounded)
__device__ __half g_wqh[786432];               // fp16 qkv_w
__device__ __half g_wph[262144];               // fp16 proj_w
__device__ __half g_atth[33554432];            // fp16 attention output
__device__ __half g_qh[1024 * 16 * 64 * 32];   // [(w,h,n),d]
__device__ __half g_kh[1024 * 16 * 64 * 32];   // [(w,h,n),d]
__device__ __half g_vh[1024 * 16 * 64 * 32];   // [(w,h,d),n]  (transposed)
__device__ __half g_bm[4 * 16 * 64 * 64];      // fused bias+mask [cls][h][n][m]

// ---------------- helpers ----------------
__device__ __forceinline__ uint32_t pack2h(float lo, float hi) {
    uint32_t r;
    asm("cvt.rn.f16x2.f32 %0, %1, %2;" : "=r"(r) : "f"(hi), "f"(lo));
    return r;
}

__device__ __forceinline__ uint32_t smem_u32(const void* p) {
    uint32_t r;
    asm("{ .reg .u64 t; cvta.to.shared.u64 t, %1; cvt.u32.u64 %0, t; }"
        : "=r"(r) : "l"(p));
    return r;
}

// fp16 MMA, fp32 accumulate: D(16x8) += A(16x16) * B(16x8)
#define MMAH(c, a0, a1, a2, a3, b0, b1)                                      \
    asm volatile(                                                            \
        "mma.sync.aligned.m16n8k16.row.col.f32.f16.f16.f32 "                 \
        "{%0,%1,%2,%3}, {%4,%5,%6,%7}, {%8,%9}, {%0,%1,%2,%3};\n"            \
        : "+f"((c)[0]), "+f"((c)[1]), "+f"((c)[2]), "+f"((c)[3])             \
        : "r"(a0), "r"(a1), "r"(a2), "r"(a3), "r"(b0), "r"(b1))

// ldmatrix x4: 4 8x8 fp16 blocks; lane 8b..8b+7 supplies row addrs of block b
#define LDSM4(r0, r1, r2, r3, addr)                                          \
    asm volatile("ldmatrix.sync.aligned.m8n8.x4.shared.b16 {%0,%1,%2,%3}, [%4];" \
                 : "=r"(r0), "=r"(r1), "=r"(r2), "=r"(r3) : "r"(addr))

#define CP_ASYNC16(dst_u32, src_ptr)                                         \
    asm volatile("cp.async.cg.shared.global [%0], [%1], 16;" ::              \
                 "r"(dst_u32), "l"(src_ptr))
#define CP_COMMIT() asm volatile("cp.async.commit_group;")
#define CP_WAIT0()  asm volatile("cp.async.wait_group 0;")
#define CP_WAIT2()  asm volatile("cp.async.wait_group 2;")

// window-token row -> original image row (shift + window partition fused).
__device__ __forceinline__ int permute_row(int r) {
    int b   = r >> 12;
    int rem = r & 4095;
    int wi  = rem >> 6, n = rem & 63;
    int hs  = ((wi >> 3) << 3) | (n >> 3);
    int ws  = ((wi & 7) << 3) | (n & 7);
    int hp  = (hs + 4) & 63;
    int wp  = (ws + 4) & 63;
    return (b << 12) | (hp << 6) | wp;
}

// ---------------- K-1: pre-round x / qkv_w / proj_w to fp16 ----------------
__global__ __launch_bounds__(1024) void k_pre(const float* __restrict__ x,
                                              const float* __restrict__ qw,
                                              const float* __restrict__ pw) {
    int i = blockIdx.x * 1024 + threadIdx.x;  // float4 index, < 8650752
    float4 v;
    __half2* dst;
    if (i < 8388608) {
        v   = ((const float4*)x)[i];
        dst = (__half2*)g_xh + (size_t)i * 2;
    } else if (i < 8585216) {
        int j = i - 8388608;
        v   = ((const float4*)qw)[j];
        dst = (__half2*)g_wqh + (size_t)j * 2;
    } else {
        int j = i - 8585216;
        v   = ((const float4*)pw)[j];
        dst = (__half2*)g_wph + (size_t)j * 2;
    }
    dst[0] = __floats2half2_rn(v.x, v.y);
    dst[1] = __floats2half2_rn(v.z, v.w);
}

// ---------------- K0: build fused bias+mask fp16 table --------------------
__global__ __launch_bounds__(256) void k_bias_pre(const float* __restrict__ bt,
                                                  const int* __restrict__ ri) {
    const int cls = blockIdx.x, h = blockIdx.y;
    __shared__ int sid[64];
    if (threadIdx.x < 64) {
        int tok = threadIdx.x;
        int rh = (cls & 2) ? (((tok >> 3) < 4) ? 1 : 2) : 0;
        int rw = (cls & 1) ? (((tok & 7) < 4) ? 1 : 2) : 0;
        sid[tok] = rh * 3 + rw;
    }
    __syncthreads();
    __half* dst = g_bm + (((size_t)cls * 16 + h) << 12);
    for (int nm = threadIdx.x; nm < 4096; nm += 256) {
        int n = nm >> 6, m = nm & 63;
        float v = bt[ri[nm] * 16 + h] + ((sid[n] != sid[m]) ? -100.f : 0.f);
        dst[nm] = __float2half(v);
    }
}

// ---------------- K1/K3: fp16 GEMM (NT), 128x128x32, 128 thr -----------------
// 4 warps x 64x64 warp tile; 4-STAGE cp.async ring; ldmatrix fragment loads
// (16 LDSM per warp per K-tile instead of 64 LDS.32).
template <bool IS_QKV>
__global__ __launch_bounds__(128, 2) void k_gemm(const float* __restrict__ bias,
                                                 float* __restrict__ outp) {
    extern __shared__ uint32_t dsm[];   // 4 stages x (A 2560 + B 2560 b32) = 80KB

    const __half* Asrc = IS_QKV ? g_xh : g_atth;
    const __half* Wsrc = IS_QKV ? g_wqh : g_wph;

    const int Cb   = blockIdx.x * 128;   // column tile (fast axis)
    const int Rb   = blockIdx.y * 128;   // row tile
    const int tid  = threadIdx.x;
    const int lane = tid & 31, wid = tid >> 5;
    const int g = lane >> 2, t = lane & 3;
    const int wm = wid & 1, wn = wid >> 1;
    const int m0 = wm * 64, n0 = wn * 64;

    const int lrow4 = tid >> 2, cc4 = tid & 3;
    const uint32_t sbase = smem_u32(dsm);

    int asrc_off[4], bsrc_off[4];
    uint32_t dstoff[4];
#pragma unroll
    for (int i = 0; i < 4; i++) {
        int row = lrow4 + i * 32;
        int src = IS_QKV ? permute_row(Rb + row) : (Rb + row);
        asrc_off[i] = src * 512 + cc4 * 8;
        bsrc_off[i] = (Cb + row) * 512 + cc4 * 8;
        dstoff[i]   = (uint32_t)(row * 20 + cc4 * 4) * 4u;
    }

    auto issue = [&](int j, int k0) {
        const uint32_t ab = sbase + (uint32_t)j * 20480u;
        const uint32_t bb = ab + 10240u;
#pragma unroll
        for (int i = 0; i < 4; i++)
            CP_ASYNC16(ab + dstoff[i], Asrc + asrc_off[i] + k0);
#pragma unroll
        for (int i = 0; i < 4; i++)
            CP_ASYNC16(bb + dstoff[i], Wsrc + bsrc_off[i] + k0);
        CP_COMMIT();
    };

    issue(0, 0); issue(1, 32); issue(2, 64);

    // ldmatrix lane-address bases (b32 units within a stage region)
    const int lq = lane & 7;
    const uint32_t a_lm = (uint32_t)((m0 + lq + ((lane >> 3) & 1) * 8) * 20 +
                                     ((lane >> 4) & 1) * 4) * 4u;
    const uint32_t b_lm = (uint32_t)((n0 + ((lane >> 4) & 1) * 8 + lq) * 20 +
                                     ((lane >> 3) & 1) * 4) * 4u;

    float acc[4][8][4];
#pragma unroll
    for (int a = 0; a < 4; a++)
#pragma unroll
        for (int b = 0; b < 8; b++)
#pragma unroll
            for (int cc = 0; cc < 4; cc++) acc[a][b][cc] = 0.f;

#pragma unroll 1
    for (int kt = 0; kt < 16; kt++) {
        CP_WAIT2();
        __syncthreads();
        if (kt < 13) issue((kt + 3) & 3, (kt + 3) * 32);
        else CP_COMMIT();

        const uint32_t Abase = sbase + (uint32_t)(kt & 3) * 20480u;
        const uint32_t Bbase = Abase + 10240u;
#pragma unroll
        for (int ks = 0; ks < 2; ks++) {
            uint32_t a[4][4];
#pragma unroll
            for (int mf = 0; mf < 4; mf++)
                LDSM4(a[mf][0], a[mf][1], a[mf][2], a[mf][3],
                      Abase + a_lm + (uint32_t)(mf * 320 + ks * 8) * 4u);
            uint32_t bfr[4][4];
#pragma unroll
            for (int ng = 0; ng < 4; ng++)
                LDSM4(bfr[ng][0], bfr[ng][1], bfr[ng][2], bfr[ng][3],
                      Bbase + b_lm + (uint32_t)(ng * 320 + ks * 8) * 4u);
#pragma unroll
            for (int nf = 0; nf < 8; nf++) {
                uint32_t b0 = bfr[nf >> 1][(nf & 1) * 2];
                uint32_t b1 = bfr[nf >> 1][(nf & 1) * 2 + 1];
#pragma unroll
                for (int mf = 0; mf < 4; mf++)
                    MMAH(acc[mf][nf], a[mf][0], a[mf][1], a[mf][2], a[mf][3], b0, b1);
            }
        }
    }
    __syncthreads();

    float* st = (float*)dsm;  // 128*65 = 8320 f32
#pragma unroll 1
    for (int hh = 0; hh < 2; hh++) {
        if (wn == hh) {
#pragma unroll
            for (int mf = 0; mf < 4; mf++)
#pragma unroll
                for (int nf = 0; nf < 8; nf++) {
                    int row = m0 + mf * 16 + g;
                    int col = nf * 8 + 2 * t;
                    st[row * 65 + col]           = acc[mf][nf][0];
                    st[row * 65 + col + 1]       = acc[mf][nf][1];
                    st[(row + 8) * 65 + col]     = acc[mf][nf][2];
                    st[(row + 8) * 65 + col + 1] = acc[mf][nf][3];
                }
        }
        __syncthreads();

        const int Co = Cb + hh * 64;
        if (IS_QKV) {
            const int s = Co >> 9;  // 0=q 1=k 2=v (uniform)
            if (s < 2) {
                __half* buf = (s == 0) ? g_qh : g_kh;
#pragma unroll
                for (int i = 0; i < 32; i++) {
                    int p  = tid + i * 128;
                    int m  = p >> 5, jj = (p & 31) * 2;
                    int r  = Rb + m, o = Co + jj;
                    int hd = (o >> 5) & 15, d = o & 31;
                    int wnd = r >> 6, n = r & 63;
                    float v0 = st[m * 65 + jj]     + bias[o];
                    float v1 = st[m * 65 + jj + 1] + bias[o + 1];
                    *(__half2*)&buf[((size_t)((wnd * 16 + hd) * 64 + n)) * 32 + d] =
                        __floats2half2_rn(v0, v1);
                }
            } else {
#pragma unroll
                for (int i = 0; i < 64; i++) {
                    int idx = tid + i * 128;
                    int m = idx & 127, jj = idx >> 7;
                    int r = Rb + m, o = Co + jj;
                    int hd = (o >> 5) & 15, d = o & 31;
                    int wnd = r >> 6, n = r & 63;
                    float v = st[m * 65 + jj] + bias[o];
                    g_vh[((size_t)((wnd * 16 + hd) * 32 + d)) * 64 + n] = __float2half(v);
                }
            }
        } else {
#pragma unroll
            for (int i = 0; i < 64; i++) {
                int idx = tid + i * 128;
                int m = idx >> 6, j = idx & 63;
                int r = Rb + m, o = Co + j;
                int dst = permute_row(r);
                outp[(size_t)dst * 512 + o] = st[m * 65 + j] + bias[o];
            }
        }
        __syncthreads();
    }
}

// ---------------- K2: attention (fp16 MMA + ldmatrix) ----------------------
__global__ __launch_bounds__(128) void k_attn() {
    __shared__ uint32_t sm[1280 + 1280 + 1152];
    uint32_t* qs  = sm;
    uint32_t* kss = sm + 1280;
    uint32_t* vst = sm + 2560;

    const int w   = blockIdx.x;
    const int h   = blockIdx.y;
    const int tid = threadIdx.x;
    const int lane = tid & 31, wid = tid >> 5;
    const int g = lane >> 2, t = lane & 3;

    const size_t base = (size_t)(w * 16 + h) * 2048;   // halves
    const float scale = 0.17677669529663687f;          // 32^-0.5

    const uint32_t qb = smem_u32(qs), kb = smem_u32(kss), vb = smem_u32(vst);
#pragma unroll
    for (int i = 0; i < 2; i++) {
        int c   = tid + i * 128;
        int row = c >> 2, cc = c & 3;
        uint32_t so = (uint32_t)(row * 20 + cc * 4) * 4u;
        CP_ASYNC16(qb + so, g_qh + base + row * 32 + cc * 8);
        CP_ASYNC16(kb + so, g_kh + base + row * 32 + cc * 8);
        int d = c >> 3, c2 = c & 7;
        CP_ASYNC16(vb + (uint32_t)(d * 36 + c2 * 4) * 4u, g_vh + base + d * 64 + c2 * 8);
    }
    CP_COMMIT();

    const int wIdx = w & 63;
    const int cls  = (((wIdx >> 3) == 7) ? 2 : 0) | (((wIdx & 7) == 7) ? 1 : 0);
    const __half2* bh2 = (const __half2*)g_bm + (((size_t)cls * 16 + h) << 11);

    // ldmatrix lane bases
    const int lq = lane & 7;
    const int m0 = wid * 16;
    const uint32_t qa_lm = (uint32_t)((m0 + lq + ((lane >> 3) & 1) * 8) * 20 +
                                      ((lane >> 4) & 1) * 4) * 4u;
    const uint32_t kb_lm = (uint32_t)((((lane >> 4) & 1) * 8 + lq) * 20 +
                                      ((lane >> 3) & 1) * 4) * 4u;
    const uint32_t v_lm  = (uint32_t)((((lane >> 4) & 1) * 8 + lq) * 36 +
                                      ((lane >> 3) & 1) * 4) * 4u;

    CP_WAIT0();
    __syncthreads();

    // S = q @ k^T  (hd=32 -> 2 k16 steps)
    float acc[8][4];
#pragma unroll
    for (int a = 0; a < 8; a++)
#pragma unroll
        for (int b = 0; b < 4; b++) acc[a][b] = 0.f;

#pragma unroll
    for (int ks = 0; ks < 2; ks++) {
        uint32_t a0, a1, a2, a3;
        LDSM4(a0, a1, a2, a3, qb + qa_lm + (uint32_t)(ks * 8) * 4u);
        uint32_t bfr[4][4];
#pragma unroll
        for (int ng = 0; ng < 4; ng++)
            LDSM4(bfr[ng][0], bfr[ng][1], bfr[ng][2], bfr[ng][3],
                  kb + kb_lm + (uint32_t)(ng * 320 + ks * 8) * 4u);
#pragma unroll
        for (int nf = 0; nf < 8; nf++)
            MMAH(acc[nf], a0, a1, a2, a3,
                 bfr[nf >> 1][(nf & 1) * 2], bfr[nf >> 1][(nf & 1) * 2 + 1]);
    }

    // scale + fused (bias+mask), softmax (rows r0/r1 per lane)
    const int r0 = m0 + g, r1 = r0 + 8;
    float mx0 = -1e30f, mx1 = -1e30f;
#pragma unroll
    for (int nf = 0; nf < 8; nf++) {
        float2 b0 = __half22float2(bh2[r0 * 32 + nf * 4 + t]);
        float2 b1 = __half22float2(bh2[r1 * 32 + nf * 4 + t]);
        acc[nf][0] = fmaf(acc[nf][0], scale, b0.x);
        acc[nf][1] = fmaf(acc[nf][1], scale, b0.y);
        acc[nf][2] = fmaf(acc[nf][2], scale, b1.x);
        acc[nf][3] = fmaf(acc[nf][3], scale, b1.y);
        mx0 = fmaxf(mx0, fmaxf(acc[nf][0], acc[nf][1]));
        mx1 = fmaxf(mx1, fmaxf(acc[nf][2], acc[nf][3]));
    }
    mx0 = fmaxf(mx0, __shfl_xor_sync(0xffffffffu, mx0, 1));
    mx0 = fmaxf(mx0, __shfl_xor_sync(0xffffffffu, mx0, 2));
    mx1 = fmaxf(mx1, __shfl_xor_sync(0xffffffffu, mx1, 1));
    mx1 = fmaxf(mx1, __shfl_xor_sync(0xffffffffu, mx1, 2));
    float s0 = 0.f, s1 = 0.f;
#pragma unroll
    for (int nf = 0; nf < 8; nf++) {
        acc[nf][0] = __expf(acc[nf][0] - mx0); s0 += acc[nf][0];
        acc[nf][1] = __expf(acc[nf][1] - mx0); s0 += acc[nf][1];
        acc[nf][2] = __expf(acc[nf][2] - mx1); s1 += acc[nf][2];
        acc[nf][3] = __expf(acc[nf][3] - mx1); s1 += acc[nf][3];
    }
    s0 += __shfl_xor_sync(0xffffffffu, s0, 1);
    s0 += __shfl_xor_sync(0xffffffffu, s0, 2);
    s1 += __shfl_xor_sync(0xffffffffu, s1, 1);
    s1 += __shfl_xor_sync(0xffffffffu, s1, 2);
    const float inv0 = 1.f / s0, inv1 = 1.f / s1;

    // O = P @ V: P packed straight from C-fragments into k16 A-operands.
    float acc2[4][4];
#pragma unroll
    for (int a = 0; a < 4; a++)
#pragma unroll
        for (int b = 0; b < 4; b++) acc2[a][b] = 0.f;
#pragma unroll
    for (int j = 0; j < 4; j++) {
        uint32_t a0 = pack2h(acc[2 * j][0] * inv0,     acc[2 * j][1] * inv0);
        uint32_t a1 = pack2h(acc[2 * j][2] * inv1,     acc[2 * j][3] * inv1);
        uint32_t a2 = pack2h(acc[2 * j + 1][0] * inv0, acc[2 * j + 1][1] * inv0);
        uint32_t a3 = pack2h(acc[2 * j + 1][2] * inv1, acc[2 * j + 1][3] * inv1);
        uint32_t vfr[2][4];
#pragma unroll
        for (int ng = 0; ng < 2; ng++)
            LDSM4(vfr[ng][0], vfr[ng][1], vfr[ng][2], vfr[ng][3],
                  vb + v_lm + (uint32_t)(ng * 576 + j * 8) * 4u);
#pragma unroll
        for (int nf = 0; nf < 4; nf++)
            MMAH(acc2[nf], a0, a1, a2, a3,
                 vfr[nf >> 1][(nf & 1) * 2], vfr[nf >> 1][(nf & 1) * 2 + 1]);
    }

    __syncthreads();
    uint32_t* osth = sm;  // fp16 staging [64][20 b32]
#pragma unroll
    for (int nf = 0; nf < 4; nf++) {
        int col = nf * 4 + t;
        osth[r0 * 20 + col] = pack2h(acc2[nf][0], acc2[nf][1]);
        osth[r1 * 20 + col] = pack2h(acc2[nf][2], acc2[nf][3]);
    }
    __syncthreads();
    __half2* outh2 = (__half2*)g_atth;
    const size_t ob2 = (size_t)(w * 64) * 256 + h * 16;
#pragma unroll
    for (int i = 0; i < 8; i++) {
        int idx = tid + i * 128;
        int row = idx >> 4, col = idx & 15;
        outh2[ob2 + (size_t)row * 256 + col] = *(__half2*)&osth[row * 20 + col];
    }
}

// ---------------- launch ----------------
static constexpr int SMEM_GEMM_BYTES = 4 * 5120 * 4;  // 81920

extern "C" void kernel_launch(void* const* d_in, const int* in_sizes, int n_in,
                              void* d_out, int out_size) {
    const float* x  = nullptr;  // 33554432
    const float* qw = nullptr;  // 786432
    const float* qb = nullptr;  // 1536
    const float* pw = nullptr;  // 262144
    const float* pb = nullptr;  // 512
    const float* bt = nullptr;  // 3600
    const int*   ri = nullptr;  // 4096
    for (int i = 0; i < n_in; i++) {
        switch (in_sizes[i]) {
            case 33554432: x  = (const float*)d_in[i]; break;
            case 786432:   qw = (const float*)d_in[i]; break;
            case 1536:     qb = (const float*)d_in[i]; break;
            case 262144:   pw = (const float*)d_in[i]; break;
            case 512:      pb = (const float*)d_in[i]; break;
            case 3600:     bt = (const float*)d_in[i]; break;
            case 4096:     ri = (const int*)d_in[i];   break;
            default: break;
        }
    }
    float* out = (float*)d_out;

    cudaFuncSetAttribute(k_gemm<true>, cudaFuncAttributeMaxDynamicSharedMemorySize,
                         SMEM_GEMM_BYTES);
    cudaFuncSetAttribute(k_gemm<false>, cudaFuncAttributeMaxDynamicSharedMemorySize,
                         SMEM_GEMM_BYTES);

    k_pre<<<8448, 1024>>>(x, qw, pw);
    k_bias_pre<<<dim3(4, 16), 256>>>(bt, ri);
    k_gemm<true><<<dim3(12, 512), 128, SMEM_GEMM_BYTES>>>(qb, nullptr);
    k_attn<<<dim3(1024, 16), 128>>>();
    k_gemm<false><<<dim3(4, 512), 128, SMEM_GEMM_BYTES>>>(pb, out);
}

// round 16
// speedup vs baseline: 1.3538x; 1.3538x over previous
#include <cuda_runtime.h>
#include <cuda_fp16.h>
#include <cstdint>

// ---------------- problem constants ----------------
// B=16, H=W=64, C=512, NH=16, hd=32, WS=8, N=64, SS=4

// ---------------- device scratch ----------------
__device__ __half g_xh[33554432];              // fp16 query (pre-rounded)
__device__ __half g_wqh[786432];               // fp16 qkv_w
__device__ __half g_wph[262144];               // fp16 proj_w
__device__ __half g_atth[33554432];            // fp16 attention output
__device__ __half g_qh[1024 * 16 * 64 * 32];   // [(w,h,n),d]
__device__ __half g_kh[1024 * 16 * 64 * 32];   // [(w,h,n),d]
__device__ __half g_vh[1024 * 16 * 64 * 32];   // [(w,h,d),n]  (transposed)
__device__ __half g_bm[4 * 16 * 64 * 64];      // fused bias+mask [cls][h][n][m]

// ---------------- helpers ----------------
__device__ __forceinline__ uint32_t pack2h(float lo, float hi) {
    uint32_t r;
    asm("cvt.rn.f16x2.f32 %0, %1, %2;" : "=r"(r) : "f"(hi), "f"(lo));
    return r;
}

__device__ __forceinline__ uint32_t smem_u32(const void* p) {
    uint32_t r;
    asm("{ .reg .u64 t; cvta.to.shared.u64 t, %1; cvt.u32.u64 %0, t; }"
        : "=r"(r) : "l"(p));
    return r;
}

// fp16 MMA, fp32 accumulate: D(16x8) += A(16x16) * B(16x8)
#define MMAH(c, a0, a1, a2, a3, b0, b1)                                      \
    asm volatile(                                                            \
        "mma.sync.aligned.m16n8k16.row.col.f32.f16.f16.f32 "                 \
        "{%0,%1,%2,%3}, {%4,%5,%6,%7}, {%8,%9}, {%0,%1,%2,%3};\n"            \
        : "+f"((c)[0]), "+f"((c)[1]), "+f"((c)[2]), "+f"((c)[3])             \
        : "r"(a0), "r"(a1), "r"(a2), "r"(a3), "r"(b0), "r"(b1))

#define CP_ASYNC16(dst_u32, src_ptr)                                         \
    asm volatile("cp.async.cg.shared.global [%0], [%1], 16;" ::              \
                 "r"(dst_u32), "l"(src_ptr))
#define CP_COMMIT() asm volatile("cp.async.commit_group;")
#define CP_WAIT0()  asm volatile("cp.async.wait_group 0;")
#define CP_WAIT1()  asm volatile("cp.async.wait_group 1;")

// window-token row -> original image row (shift + window partition fused).
__device__ __forceinline__ int permute_row(int r) {
    int b   = r >> 12;
    int rem = r & 4095;
    int wi  = rem >> 6, n = rem & 63;
    int hs  = ((wi >> 3) << 3) | (n >> 3);
    int ws  = ((wi & 7) << 3) | (n & 7);
    int hp  = (hs + 4) & 63;
    int wp  = (ws + 4) & 63;
    return (b << 12) | (hp << 6) | wp;
}

// ---------------- K-1: pre-round x / qkv_w / proj_w to fp16 ----------------
__global__ __launch_bounds__(1024) void k_pre(const float* __restrict__ x,
                                              const float* __restrict__ qw,
                                              const float* __restrict__ pw) {
    int i = blockIdx.x * 1024 + threadIdx.x;  // float4 index, < 8650752
    float4 v;
    __half2* dst;
    if (i < 8388608) {
        v   = ((const float4*)x)[i];
        dst = (__half2*)g_xh + (size_t)i * 2;
    } else if (i < 8585216) {
        int j = i - 8388608;
        v   = ((const float4*)qw)[j];
        dst = (__half2*)g_wqh + (size_t)j * 2;
    } else {
        int j = i - 8585216;
        v   = ((const float4*)pw)[j];
        dst = (__half2*)g_wph + (size_t)j * 2;
    }
    dst[0] = __floats2half2_rn(v.x, v.y);
    dst[1] = __floats2half2_rn(v.z, v.w);
}

// ---------------- K0: build fused bias+mask fp16 table --------------------
// blockIdx.x = window class (bit1: wi_h==7, bit0: wi_w==7), blockIdx.y = head
__global__ __launch_bounds__(256) void k_bias_pre(const float* __restrict__ bt,
                                                  const int* __restrict__ ri) {
    const int cls = blockIdx.x, h = blockIdx.y;
    __shared__ int sid[64];
    if (threadIdx.x < 64) {
        int tok = threadIdx.x;
        int rh = (cls & 2) ? (((tok >> 3) < 4) ? 1 : 2) : 0;
        int rw = (cls & 1) ? (((tok & 7) < 4) ? 1 : 2) : 0;
        sid[tok] = rh * 3 + rw;
    }
    __syncthreads();
    __half* dst = g_bm + (((size_t)cls * 16 + h) << 12);
    for (int nm = threadIdx.x; nm < 4096; nm += 256) {
        int n = nm >> 6, m = nm & 63;
        float v = bt[ri[nm] * 16 + h] + ((sid[n] != sid[m]) ? -100.f : 0.f);
        dst[nm] = __float2half(v);
    }
}

// ---------------- K1/K3: fp16 GEMM (NT), 128x128x32, 128 thr -----------------
// 4 warps x 64x64 warp tile; 3-STAGE cp.async ring (2 tiles in flight) so
// THREE CTAs fit per SM (60KB smem each) -> 12 warps/SM of MMA issue.
template <bool IS_QKV>
__global__ __launch_bounds__(128, 3) void k_gemm(const float* __restrict__ bias,
                                                 float* __restrict__ outp) {
    extern __shared__ uint32_t dsm[];   // 3 stages x (A 2560 + B 2560 b32) = 60KB

    const __half* Asrc = IS_QKV ? g_xh : g_atth;
    const __half* Wsrc = IS_QKV ? g_wqh : g_wph;

    const int Cb   = blockIdx.x * 128;   // column tile (fast axis)
    const int Rb   = blockIdx.y * 128;   // row tile
    const int tid  = threadIdx.x;
    const int lane = tid & 31, wid = tid >> 5;
    const int g = lane >> 2, t = lane & 3;
    const int wm = wid & 1, wn = wid >> 1;
    const int m0 = wm * 64, n0 = wn * 64;

    const int lrow4 = tid >> 2, cc4 = tid & 3;
    const uint32_t sbase = smem_u32(dsm);

    int asrc_off[4], bsrc_off[4];
    uint32_t dstoff[4];
#pragma unroll
    for (int i = 0; i < 4; i++) {
        int row = lrow4 + i * 32;
        int src = IS_QKV ? permute_row(Rb + row) : (Rb + row);
        asrc_off[i] = src * 512 + cc4 * 8;
        bsrc_off[i] = (Cb + row) * 512 + cc4 * 8;
        dstoff[i]   = (uint32_t)(row * 20 + cc4 * 4) * 4u;
    }

    auto issue = [&](int j, int k0) {
        const uint32_t ab = sbase + (uint32_t)j * 20480u;
        const uint32_t bb = ab + 10240u;
#pragma unroll
        for (int i = 0; i < 4; i++)
            CP_ASYNC16(ab + dstoff[i], Asrc + asrc_off[i] + k0);
#pragma unroll
        for (int i = 0; i < 4; i++)
            CP_ASYNC16(bb + dstoff[i], Wsrc + bsrc_off[i] + k0);
        CP_COMMIT();
    };

    issue(0, 0); issue(1, 32);

    float acc[4][8][4];
#pragma unroll
    for (int a = 0; a < 4; a++)
#pragma unroll
        for (int b = 0; b < 8; b++)
#pragma unroll
            for (int cc = 0; cc < 4; cc++) acc[a][b][cc] = 0.f;

    int stage = 0, nxt = 2;
#pragma unroll 1
    for (int kt = 0; kt < 16; kt++) {
        CP_WAIT1();          // tile kt landed (kt+1 may still fly)
        __syncthreads();     // all warps past kt-1 MMAs; data visible
        if (kt < 14) issue(nxt, (kt + 2) * 32);
        else CP_COMMIT();    // empty group keeps outstanding count uniform

        const uint32_t* A = dsm + stage * 5120;
        const uint32_t* B = A + 2560;
#pragma unroll
        for (int ks = 0; ks < 2; ks++) {
            const int kk = ks * 8 + t;
            uint32_t a[4][4];
#pragma unroll
            for (int mf = 0; mf < 4; mf++) {
                int base = (m0 + mf * 16 + g) * 20 + kk;
                a[mf][0] = A[base];
                a[mf][1] = A[base + 160];
                a[mf][2] = A[base + 4];
                a[mf][3] = A[base + 164];
            }
#pragma unroll
            for (int nf = 0; nf < 8; nf++) {
                int nb      = (n0 + nf * 8 + g) * 20 + kk;
                uint32_t b0 = B[nb], b1 = B[nb + 4];
#pragma unroll
                for (int mf = 0; mf < 4; mf++)
                    MMAH(acc[mf][nf], a[mf][0], a[mf][1], a[mf][2], a[mf][3], b0, b1);
            }
        }
        stage = (stage == 2) ? 0 : stage + 1;
        nxt   = (nxt == 2) ? 0 : nxt + 1;
    }
    __syncthreads();

    // epilogue: two 128x64 halves staged through smem
    float* st = (float*)dsm;  // 128*65 = 8320 f32 <= 15360 b32
#pragma unroll 1
    for (int hh = 0; hh < 2; hh++) {
        if (wn == hh) {
#pragma unroll
            for (int mf = 0; mf < 4; mf++)
#pragma unroll
                for (int nf = 0; nf < 8; nf++) {
                    int row = m0 + mf * 16 + g;
                    int col = nf * 8 + 2 * t;
                    st[row * 65 + col]           = acc[mf][nf][0];
                    st[row * 65 + col + 1]       = acc[mf][nf][1];
                    st[(row + 8) * 65 + col]     = acc[mf][nf][2];
                    st[(row + 8) * 65 + col + 1] = acc[mf][nf][3];
                }
        }
        __syncthreads();

        const int Co = Cb + hh * 64;
        if (IS_QKV) {
            const int s = Co >> 9;  // 0=q 1=k 2=v (uniform)
            if (s < 2) {
                __half* buf = (s == 0) ? g_qh : g_kh;
#pragma unroll
                for (int i = 0; i < 32; i++) {
                    int p  = tid + i * 128;
                    int m  = p >> 5, jj = (p & 31) * 2;
                    int r  = Rb + m, o = Co + jj;
                    int hd = (o >> 5) & 15, d = o & 31;
                    int wnd = r >> 6, n = r & 63;
                    float v0 = st[m * 65 + jj]     + bias[o];
                    float v1 = st[m * 65 + jj + 1] + bias[o + 1];
                    *(__half2*)&buf[((size_t)((wnd * 16 + hd) * 64 + n)) * 32 + d] =
                        __floats2half2_rn(v0, v1);
                }
            } else {
                // V transposed: [(w,h,d), n]; m-fast -> coalesced n
#pragma unroll
                for (int i = 0; i < 64; i++) {
                    int idx = tid + i * 128;
                    int m = idx & 127, jj = idx >> 7;
                    int r = Rb + m, o = Co + jj;
                    int hd = (o >> 5) & 15, d = o & 31;
                    int wnd = r >> 6, n = r & 63;
                    float v = st[m * 65 + jj] + bias[o];
                    g_vh[((size_t)((wnd * 16 + hd) * 32 + d)) * 64 + n] = __float2half(v);
                }
            }
        } else {
#pragma unroll
            for (int i = 0; i < 64; i++) {
                int idx = tid + i * 128;
                int m = idx >> 6, j = idx & 63;
                int r = Rb + m, o = Co + j;
                int dst = permute_row(r);
                outp[(size_t)dst * 512 + o] = st[m * 65 + j] + bias[o];
            }
        }
        __syncthreads();
    }
}

// ---------------- K2: attention (fp16 MMA), one block per (window, head) ----
__global__ __launch_bounds__(128) void k_attn() {
    __shared__ uint32_t sm[1280 + 1280 + 1152];
    uint32_t* qs  = sm;
    uint32_t* kss = sm + 1280;
    uint32_t* vst = sm + 2560;

    const int w   = blockIdx.x;
    const int h   = blockIdx.y;
    const int tid = threadIdx.x;
    const int lane = tid & 31, wid = tid >> 5;
    const int g = lane >> 2, t = lane & 3;

    const size_t base = (size_t)(w * 16 + h) * 2048;   // halves
    const float scale = 0.17677669529663687f;          // 32^-0.5

    const uint32_t qb = smem_u32(qs), kb = smem_u32(kss), vb = smem_u32(vst);
#pragma unroll
    for (int i = 0; i < 2; i++) {
        int c   = tid + i * 128;
        int row = c >> 2, cc = c & 3;
        uint32_t so = (uint32_t)(row * 20 + cc * 4) * 4u;
        CP_ASYNC16(qb + so, g_qh + base + row * 32 + cc * 8);
        CP_ASYNC16(kb + so, g_kh + base + row * 32 + cc * 8);
        int d = c >> 3, c2 = c & 7;
        CP_ASYNC16(vb + (uint32_t)(d * 36 + c2 * 4) * 4u, g_vh + base + d * 64 + c2 * 8);
    }
    CP_COMMIT();

    // fused bias+mask table pointer (half2): class from window position
    const int wIdx = w & 63;
    const int cls  = (((wIdx >> 3) == 7) ? 2 : 0) | (((wIdx & 7) == 7) ? 1 : 0);
    const __half2* bh2 = (const __half2*)g_bm + (((size_t)cls * 16 + h) << 11);

    CP_WAIT0();
    __syncthreads();

    // S = q @ k^T  (hd=32 -> 2 k16 steps)
    const int m0 = wid * 16;
    float acc[8][4];
#pragma unroll
    for (int a = 0; a < 8; a++)
#pragma unroll
        for (int b = 0; b < 4; b++) acc[a][b] = 0.f;

#pragma unroll
    for (int ks = 0; ks < 2; ks++) {
        const int kk = ks * 8 + t;
        int ab = (m0 + g) * 20 + kk;
        uint32_t a0 = qs[ab], a1 = qs[ab + 160], a2 = qs[ab + 4], a3 = qs[ab + 164];
#pragma unroll
        for (int nf = 0; nf < 8; nf++) {
            int nb = (nf * 8 + g) * 20 + kk;
            MMAH(acc[nf], a0, a1, a2, a3, kss[nb], kss[nb + 4]);
        }
    }

    // scale + fused (bias+mask), softmax (rows r0/r1 per lane)
    const int r0 = m0 + g, r1 = r0 + 8;
    float mx0 = -1e30f, mx1 = -1e30f;
#pragma unroll
    for (int nf = 0; nf < 8; nf++) {
        float2 b0 = __half22float2(bh2[r0 * 32 + nf * 4 + t]);
        float2 b1 = __half22float2(bh2[r1 * 32 + nf * 4 + t]);
        acc[nf][0] = fmaf(acc[nf][0], scale, b0.x);
        acc[nf][1] = fmaf(acc[nf][1], scale, b0.y);
        acc[nf][2] = fmaf(acc[nf][2], scale, b1.x);
        acc[nf][3] = fmaf(acc[nf][3], scale, b1.y);
        mx0 = fmaxf(mx0, fmaxf(acc[nf][0], acc[nf][1]));
        mx1 = fmaxf(mx1, fmaxf(acc[nf][2], acc[nf][3]));
    }
    mx0 = fmaxf(mx0, __shfl_xor_sync(0xffffffffu, mx0, 1));
    mx0 = fmaxf(mx0, __shfl_xor_sync(0xffffffffu, mx0, 2));
    mx1 = fmaxf(mx1, __shfl_xor_sync(0xffffffffu, mx1, 1));
    mx1 = fmaxf(mx1, __shfl_xor_sync(0xffffffffu, mx1, 2));
    float s0 = 0.f, s1 = 0.f;
#pragma unroll
    for (int nf = 0; nf < 8; nf++) {
        acc[nf][0] = __expf(acc[nf][0] - mx0); s0 += acc[nf][0];
        acc[nf][1] = __expf(acc[nf][1] - mx0); s0 += acc[nf][1];
        acc[nf][2] = __expf(acc[nf][2] - mx1); s1 += acc[nf][2];
        acc[nf][3] = __expf(acc[nf][3] - mx1); s1 += acc[nf][3];
    }
    s0 += __shfl_xor_sync(0xffffffffu, s0, 1);
    s0 += __shfl_xor_sync(0xffffffffu, s0, 2);
    s1 += __shfl_xor_sync(0xffffffffu, s1, 1);
    s1 += __shfl_xor_sync(0xffffffffu, s1, 2);
    const float inv0 = 1.f / s0, inv1 = 1.f / s1;

    // O = P @ V: P packed straight from C-fragments into k16 A-operands.
    float acc2[4][4];
#pragma unroll
    for (int a = 0; a < 4; a++)
#pragma unroll
        for (int b = 0; b < 4; b++) acc2[a][b] = 0.f;
#pragma unroll
    for (int j = 0; j < 4; j++) {
        uint32_t a0 = pack2h(acc[2 * j][0] * inv0,     acc[2 * j][1] * inv0);
        uint32_t a1 = pack2h(acc[2 * j][2] * inv1,     acc[2 * j][3] * inv1);
        uint32_t a2 = pack2h(acc[2 * j + 1][0] * inv0, acc[2 * j + 1][1] * inv0);
        uint32_t a3 = pack2h(acc[2 * j + 1][2] * inv1, acc[2 * j + 1][3] * inv1);
        const int kk = j * 8 + t;
#pragma unroll
        for (int nf = 0; nf < 4; nf++) {
            int nb = (nf * 8 + g) * 36 + kk;
            MMAH(acc2[nf], a0, a1, a2, a3, vst[nb], vst[nb + 4]);
        }
    }

    __syncthreads();
    uint32_t* osth = sm;  // fp16 staging [64][20 b32]
#pragma unroll
    for (int nf = 0; nf < 4; nf++) {
        int col = nf * 4 + t;
        osth[r0 * 20 + col] = pack2h(acc2[nf][0], acc2[nf][1]);
        osth[r1 * 20 + col] = pack2h(acc2[nf][2], acc2[nf][3]);
    }
    __syncthreads();
    __half2* outh2 = (__half2*)g_atth;
    const size_t ob2 = (size_t)(w * 64) * 256 + h * 16;
#pragma unroll
    for (int i = 0; i < 8; i++) {
        int idx = tid + i * 128;
        int row = idx >> 4, col = idx & 15;
        outh2[ob2 + (size_t)row * 256 + col] = *(__half2*)&osth[row * 20 + col];
    }
}

// ---------------- launch ----------------
static constexpr int SMEM_GEMM_BYTES = 3 * 5120 * 4;  // 61440

extern "C" void kernel_launch(void* const* d_in, const int* in_sizes, int n_in,
                              void* d_out, int out_size) {
    const float* x  = nullptr;  // 33554432
    const float* qw = nullptr;  // 786432
    const float* qb = nullptr;  // 1536
    const float* pw = nullptr;  // 262144
    const float* pb = nullptr;  // 512
    const float* bt = nullptr;  // 3600
    const int*   ri = nullptr;  // 4096
    for (int i = 0; i < n_in; i++) {
        switch (in_sizes[i]) {
            case 33554432: x  = (const float*)d_in[i]; break;
            case 786432:   qw = (const float*)d_in[i]; break;
            case 1536:     qb = (const float*)d_in[i]; break;
            case 262144:   pw = (const float*)d_in[i]; break;
            case 512:      pb = (const float*)d_in[i]; break;
            case 3600:     bt = (const float*)d_in[i]; break;
            case 4096:     ri = (const int*)d_in[i];   break;
            default: break;
        }
    }
    float* out = (float*)d_out;

    cudaFuncSetAttribute(k_gemm<true>, cudaFuncAttributeMaxDynamicSharedMemorySize,
                         SMEM_GEMM_BYTES);
    cudaFuncSetAttribute(k_gemm<false>, cudaFuncAttributeMaxDynamicSharedMemorySize,
                         SMEM_GEMM_BYTES);

    k_pre<<<8448, 1024>>>(x, qw, pw);
    k_bias_pre<<<dim3(4, 16), 256>>>(bt, ri);
    k_gemm<true><<<dim3(12, 512), 128, SMEM_GEMM_BYTES>>>(qb, nullptr);
    k_attn<<<dim3(1024, 16), 128>>>();
    k_gemm<false><<<dim3(4, 512), 128, SMEM_GEMM_BYTES>>>(pb, out);
}

// round 17
// speedup vs baseline: 1.3857x; 1.0236x over previous
#include <cuda_runtime.h>
#include <cuda_fp16.h>
#include <cstdint>

// ---------------- problem constants ----------------
// B=16, H=W=64, C=512, NH=16, hd=32, WS=8, N=64, SS=4

// ---------------- device scratch ----------------
__device__ __half g_xh[33554432];              // fp16 query (pre-rounded)
__device__ __half g_wqh[786432];               // fp16 qkv_w
__device__ __half g_wph[262144];               // fp16 proj_w
__device__ __half g_atth[33554432];            // fp16 attention output
__device__ __half g_qh[1024 * 16 * 64 * 32];   // [(w,h,n),d]
__device__ __half g_kh[1024 * 16 * 64 * 32];   // [(w,h,n),d]
__device__ __half g_vh[1024 * 16 * 64 * 32];   // [(w,h,d),n]  (transposed)
__device__ __half g_bm[4 * 16 * 64 * 64];      // fused bias+mask [cls][h][n][m]

// ---------------- helpers ----------------
__device__ __forceinline__ uint32_t pack2h(float lo, float hi) {
    uint32_t r;
    asm("cvt.rn.f16x2.f32 %0, %1, %2;" : "=r"(r) : "f"(hi), "f"(lo));
    return r;
}

__device__ __forceinline__ uint32_t smem_u32(const void* p) {
    uint32_t r;
    asm("{ .reg .u64 t; cvta.to.shared.u64 t, %1; cvt.u32.u64 %0, t; }"
        : "=r"(r) : "l"(p));
    return r;
}

// fp16 MMA, fp32 accumulate: D(16x8) += A(16x16) * B(16x8)
#define MMAH(c, a0, a1, a2, a3, b0, b1)                                      \
    asm volatile(                                                            \
        "mma.sync.aligned.m16n8k16.row.col.f32.f16.f16.f32 "                 \
        "{%0,%1,%2,%3}, {%4,%5,%6,%7}, {%8,%9}, {%0,%1,%2,%3};\n"            \
        : "+f"((c)[0]), "+f"((c)[1]), "+f"((c)[2]), "+f"((c)[3])             \
        : "r"(a0), "r"(a1), "r"(a2), "r"(a3), "r"(b0), "r"(b1))

#define CP_ASYNC16(dst_u32, src_ptr)                                         \
    asm volatile("cp.async.cg.shared.global [%0], [%1], 16;" ::              \
                 "r"(dst_u32), "l"(src_ptr))
#define CP_COMMIT() asm volatile("cp.async.commit_group;")
#define CP_WAIT0()  asm volatile("cp.async.wait_group 0;")
#define CP_WAIT2()  asm volatile("cp.async.wait_group 2;")

// window-token row -> original image row (shift + window partition fused).
__device__ __forceinline__ int permute_row(int r) {
    int b   = r >> 12;
    int rem = r & 4095;
    int wi  = rem >> 6, n = rem & 63;
    int hs  = ((wi >> 3) << 3) | (n >> 3);
    int ws  = ((wi & 7) << 3) | (n & 7);
    int hp  = (hs + 4) & 63;
    int wp  = (ws + 4) & 63;
    return (b << 12) | (hp << 6) | wp;
}

// ---------------- K-1: pre-round x / qkv_w / proj_w to fp16 ----------------
// 2 float4 per thread (4224 blocks)
__global__ __launch_bounds__(1024) void k_pre(const float* __restrict__ x,
                                              const float* __restrict__ qw,
                                              const float* __restrict__ pw) {
#pragma unroll
    for (int u = 0; u < 2; u++) {
        int i = (blockIdx.x * 2 + u) * 1024 + threadIdx.x;  // float4 idx < 8650752
        float4 v;
        __half2* dst;
        if (i < 8388608) {
            v   = ((const float4*)x)[i];
            dst = (__half2*)g_xh + (size_t)i * 2;
        } else if (i < 8585216) {
            int j = i - 8388608;
            v   = ((const float4*)qw)[j];
            dst = (__half2*)g_wqh + (size_t)j * 2;
        } else {
            int j = i - 8585216;
            v   = ((const float4*)pw)[j];
            dst = (__half2*)g_wph + (size_t)j * 2;
        }
        dst[0] = __floats2half2_rn(v.x, v.y);
        dst[1] = __floats2half2_rn(v.z, v.w);
    }
}

// ---------------- K0: build fused bias+mask fp16 table --------------------
// blockIdx.x = window class (bit1: wi_h==7, bit0: wi_w==7), blockIdx.y = head
__global__ __launch_bounds__(256) void k_bias_pre(const float* __restrict__ bt,
                                                  const int* __restrict__ ri) {
    const int cls = blockIdx.x, h = blockIdx.y;
    __shared__ int sid[64];
    if (threadIdx.x < 64) {
        int tok = threadIdx.x;
        int rh = (cls & 2) ? (((tok >> 3) < 4) ? 1 : 2) : 0;
        int rw = (cls & 1) ? (((tok & 7) < 4) ? 1 : 2) : 0;
        sid[tok] = rh * 3 + rw;
    }
    __syncthreads();
    __half* dst = g_bm + (((size_t)cls * 16 + h) << 12);
    for (int nm = threadIdx.x; nm < 4096; nm += 256) {
        int n = nm >> 6, m = nm & 63;
        float v = bt[ri[nm] * 16 + h] + ((sid[n] != sid[m]) ? -100.f : 0.f);
        dst[nm] = __float2half(v);
    }
}

// ---------------- K1/K3: fp16 GEMM (NT), 128x128x32, 128 thr -----------------
// R14 config: 4 warps x 64x64 warp tile; 4-STAGE cp.async ring (3 in flight),
// 2 CTAs/SM (80KB dynamic smem).
template <bool IS_QKV>
__global__ __launch_bounds__(128, 2) void k_gemm(const float* __restrict__ bias,
                                                 float* __restrict__ outp) {
    extern __shared__ uint32_t dsm[];   // 4 stages x (A 2560 + B 2560 b32) = 80KB

    const __half* Asrc = IS_QKV ? g_xh : g_atth;
    const __half* Wsrc = IS_QKV ? g_wqh : g_wph;

    const int Cb   = blockIdx.x * 128;   // column tile (fast axis)
    const int Rb   = blockIdx.y * 128;   // row tile
    const int tid  = threadIdx.x;
    const int lane = tid & 31, wid = tid >> 5;
    const int g = lane >> 2, t = lane & 3;
    const int wm = wid & 1, wn = wid >> 1;
    const int m0 = wm * 64, n0 = wn * 64;

    const int lrow4 = tid >> 2, cc4 = tid & 3;
    const uint32_t sbase = smem_u32(dsm);

    int asrc_off[4], bsrc_off[4];
    uint32_t dstoff[4];
#pragma unroll
    for (int i = 0; i < 4; i++) {
        int row = lrow4 + i * 32;
        int src = IS_QKV ? permute_row(Rb + row) : (Rb + row);
        asrc_off[i] = src * 512 + cc4 * 8;
        bsrc_off[i] = (Cb + row) * 512 + cc4 * 8;
        dstoff[i]   = (uint32_t)(row * 20 + cc4 * 4) * 4u;
    }

    auto issue = [&](int j, int k0) {
        const uint32_t ab = sbase + (uint32_t)j * 20480u;
        const uint32_t bb = ab + 10240u;
#pragma unroll
        for (int i = 0; i < 4; i++)
            CP_ASYNC16(ab + dstoff[i], Asrc + asrc_off[i] + k0);
#pragma unroll
        for (int i = 0; i < 4; i++)
            CP_ASYNC16(bb + dstoff[i], Wsrc + bsrc_off[i] + k0);
        CP_COMMIT();
    };

    issue(0, 0); issue(1, 32); issue(2, 64);

    float acc[4][8][4];
#pragma unroll
    for (int a = 0; a < 4; a++)
#pragma unroll
        for (int b = 0; b < 8; b++)
#pragma unroll
            for (int cc = 0; cc < 4; cc++) acc[a][b][cc] = 0.f;

#pragma unroll 1
    for (int kt = 0; kt < 16; kt++) {
        CP_WAIT2();          // tile kt landed (kt+1, kt+2 may still fly)
        __syncthreads();     // all warps past kt-1 MMAs; data visible
        if (kt < 13) issue((kt + 3) & 3, (kt + 3) * 32);
        else CP_COMMIT();    // empty group keeps outstanding count at 3

        const uint32_t* A = dsm + (kt & 3) * 5120;
        const uint32_t* B = A + 2560;
#pragma unroll
        for (int ks = 0; ks < 2; ks++) {
            const int kk = ks * 8 + t;
            uint32_t a[4][4];
#pragma unroll
            for (int mf = 0; mf < 4; mf++) {
                int base = (m0 + mf * 16 + g) * 20 + kk;
                a[mf][0] = A[base];
                a[mf][1] = A[base + 160];
                a[mf][2] = A[base + 4];
                a[mf][3] = A[base + 164];
            }
#pragma unroll
            for (int nf = 0; nf < 8; nf++) {
                int nb      = (n0 + nf * 8 + g) * 20 + kk;
                uint32_t b0 = B[nb], b1 = B[nb + 4];
#pragma unroll
                for (int mf = 0; mf < 4; mf++)
                    MMAH(acc[mf][nf], a[mf][0], a[mf][1], a[mf][2], a[mf][3], b0, b1);
            }
        }
    }
    __syncthreads();

    // epilogue: two 128x64 halves staged through smem
    float* st = (float*)dsm;  // 128*65 = 8320 f32
#pragma unroll 1
    for (int hh = 0; hh < 2; hh++) {
        if (wn == hh) {
#pragma unroll
            for (int mf = 0; mf < 4; mf++)
#pragma unroll
                for (int nf = 0; nf < 8; nf++) {
                    int row = m0 + mf * 16 + g;
                    int col = nf * 8 + 2 * t;
                    st[row * 65 + col]           = acc[mf][nf][0];
                    st[row * 65 + col + 1]       = acc[mf][nf][1];
                    st[(row + 8) * 65 + col]     = acc[mf][nf][2];
                    st[(row + 8) * 65 + col + 1] = acc[mf][nf][3];
                }
        }
        __syncthreads();

        const int Co = Cb + hh * 64;
        if (IS_QKV) {
            const int s = Co >> 9;  // 0=q 1=k 2=v (uniform)
            if (s < 2) {
                __half* buf = (s == 0) ? g_qh : g_kh;
#pragma unroll
                for (int i = 0; i < 32; i++) {
                    int p  = tid + i * 128;
                    int m  = p >> 5, jj = (p & 31) * 2;
                    int r  = Rb + m, o = Co + jj;
                    int hd = (o >> 5) & 15, d = o & 31;
                    int wnd = r >> 6, n = r & 63;
                    float v0 = st[m * 65 + jj]     + bias[o];
                    float v1 = st[m * 65 + jj + 1] + bias[o + 1];
                    *(__half2*)&buf[((size_t)((wnd * 16 + hd) * 64 + n)) * 32 + d] =
                        __floats2half2_rn(v0, v1);
                }
            } else {
                // V transposed: [(w,h,d), n]; m-fast -> coalesced n
#pragma unroll
                for (int i = 0; i < 64; i++) {
                    int idx = tid + i * 128;
                    int m = idx & 127, jj = idx >> 7;
                    int r = Rb + m, o = Co + jj;
                    int hd = (o >> 5) & 15, d = o & 31;
                    int wnd = r >> 6, n = r & 63;
                    float v = st[m * 65 + jj] + bias[o];
                    g_vh[((size_t)((wnd * 16 + hd) * 32 + d)) * 64 + n] = __float2half(v);
                }
            }
        } else {
#pragma unroll
            for (int i = 0; i < 64; i++) {
                int idx = tid + i * 128;
                int m = idx >> 6, j = idx & 63;
                int r = Rb + m, o = Co + j;
                int dst = permute_row(r);
                outp[(size_t)dst * 512 + o] = st[m * 65 + j] + bias[o];
            }
        }
        __syncthreads();
    }
}

// ---------------- K2: attention (fp16 MMA), one block per (window, head) ----
__global__ __launch_bounds__(128) void k_attn() {
    __shared__ uint32_t sm[1280 + 1280 + 1152];
    uint32_t* qs  = sm;
    uint32_t* kss = sm + 1280;
    uint32_t* vst = sm + 2560;

    const int w   = blockIdx.x;
    const int h   = blockIdx.y;
    const int tid = threadIdx.x;
    const int lane = tid & 31, wid = tid >> 5;
    const int g = lane >> 2, t = lane & 3;

    const size_t base = (size_t)(w * 16 + h) * 2048;   // halves
    const float scale = 0.17677669529663687f;          // 32^-0.5

    const uint32_t qb = smem_u32(qs), kb = smem_u32(kss), vb = smem_u32(vst);
#pragma unroll
    for (int i = 0; i < 2; i++) {
        int c   = tid + i * 128;
        int row = c >> 2, cc = c & 3;
        uint32_t so = (uint32_t)(row * 20 + cc * 4) * 4u;
        CP_ASYNC16(qb + so, g_qh + base + row * 32 + cc * 8);
        CP_ASYNC16(kb + so, g_kh + base + row * 32 + cc * 8);
        int d = c >> 3, c2 = c & 7;
        CP_ASYNC16(vb + (uint32_t)(d * 36 + c2 * 4) * 4u, g_vh + base + d * 64 + c2 * 8);
    }
    CP_COMMIT();

    // fused bias+mask table pointer (half2): class from window position
    const int wIdx = w & 63;
    const int cls  = (((wIdx >> 3) == 7) ? 2 : 0) | (((wIdx & 7) == 7) ? 1 : 0);
    const __half2* bh2 = (const __half2*)g_bm + (((size_t)cls * 16 + h) << 11);

    CP_WAIT0();
    __syncthreads();

    // S = q @ k^T  (hd=32 -> 2 k16 steps)
    const int m0 = wid * 16;
    float acc[8][4];
#pragma unroll
    for (int a = 0; a < 8; a++)
#pragma unroll
        for (int b = 0; b < 4; b++) acc[a][b] = 0.f;

#pragma unroll
    for (int ks = 0; ks < 2; ks++) {
        const int kk = ks * 8 + t;
        int ab = (m0 + g) * 20 + kk;
        uint32_t a0 = qs[ab], a1 = qs[ab + 160], a2 = qs[ab + 4], a3 = qs[ab + 164];
#pragma unroll
        for (int nf = 0; nf < 8; nf++) {
            int nb = (nf * 8 + g) * 20 + kk;
            MMAH(acc[nf], a0, a1, a2, a3, kss[nb], kss[nb + 4]);
        }
    }

    // scale + fused (bias+mask), softmax (rows r0/r1 per lane)
    const int r0 = m0 + g, r1 = r0 + 8;
    float mx0 = -1e30f, mx1 = -1e30f;
#pragma unroll
    for (int nf = 0; nf < 8; nf++) {
        float2 b0 = __half22float2(bh2[r0 * 32 + nf * 4 + t]);
        float2 b1 = __half22float2(bh2[r1 * 32 + nf * 4 + t]);
        acc[nf][0] = fmaf(acc[nf][0], scale, b0.x);
        acc[nf][1] = fmaf(acc[nf][1], scale, b0.y);
        acc[nf][2] = fmaf(acc[nf][2], scale, b1.x);
        acc[nf][3] = fmaf(acc[nf][3], scale, b1.y);
        mx0 = fmaxf(mx0, fmaxf(acc[nf][0], acc[nf][1]));
        mx1 = fmaxf(mx1, fmaxf(acc[nf][2], acc[nf][3]));
    }
    mx0 = fmaxf(mx0, __shfl_xor_sync(0xffffffffu, mx0, 1));
    mx0 = fmaxf(mx0, __shfl_xor_sync(0xffffffffu, mx0, 2));
    mx1 = fmaxf(mx1, __shfl_xor_sync(0xffffffffu, mx1, 1));
    mx1 = fmaxf(mx1, __shfl_xor_sync(0xffffffffu, mx1, 2));
    float s0 = 0.f, s1 = 0.f;
#pragma unroll
    for (int nf = 0; nf < 8; nf++) {
        acc[nf][0] = __expf(acc[nf][0] - mx0); s0 += acc[nf][0];
        acc[nf][1] = __expf(acc[nf][1] - mx0); s0 += acc[nf][1];
        acc[nf][2] = __expf(acc[nf][2] - mx1); s1 += acc[nf][2];
        acc[nf][3] = __expf(acc[nf][3] - mx1); s1 += acc[nf][3];
    }
    s0 += __shfl_xor_sync(0xffffffffu, s0, 1);
    s0 += __shfl_xor_sync(0xffffffffu, s0, 2);
    s1 += __shfl_xor_sync(0xffffffffu, s1, 1);
    s1 += __shfl_xor_sync(0xffffffffu, s1, 2);
    const float inv0 = 1.f / s0, inv1 = 1.f / s1;

    // O = P @ V: P packed straight from C-fragments into k16 A-operands.
    float acc2[4][4];
#pragma unroll
    for (int a = 0; a < 4; a++)
#pragma unroll
        for (int b = 0; b < 4; b++) acc2[a][b] = 0.f;
#pragma unroll
    for (int j = 0; j < 4; j++) {
        uint32_t a0 = pack2h(acc[2 * j][0] * inv0,     acc[2 * j][1] * inv0);
        uint32_t a1 = pack2h(acc[2 * j][2] * inv1,     acc[2 * j][3] * inv1);
        uint32_t a2 = pack2h(acc[2 * j + 1][0] * inv0, acc[2 * j + 1][1] * inv0);
        uint32_t a3 = pack2h(acc[2 * j + 1][2] * inv1, acc[2 * j + 1][3] * inv1);
        const int kk = j * 8 + t;
#pragma unroll
        for (int nf = 0; nf < 4; nf++) {
            int nb = (nf * 8 + g) * 36 + kk;
            MMAH(acc2[nf], a0, a1, a2, a3, vst[nb], vst[nb + 4]);
        }
    }

    // direct register -> gmem store (no smem staging, no extra syncs).
    // thread owns rows r0/r1, half2 cols nf*4+t of the 32-col (16 half2) d-range
    __half2* outh2 = (__half2*)g_atth;
    const size_t ob2 = (size_t)(w * 64) * 256 + h * 16;
#pragma unroll
    for (int nf = 0; nf < 4; nf++) {
        int col = nf * 4 + t;
        outh2[ob2 + (size_t)r0 * 256 + col] = __floats2half2_rn(acc2[nf][0], acc2[nf][1]);
        outh2[ob2 + (size_t)r1 * 256 + col] = __floats2half2_rn(acc2[nf][2], acc2[nf][3]);
    }
}

// ---------------- launch ----------------
static constexpr int SMEM_GEMM_BYTES = 4 * 5120 * 4;  // 81920

extern "C" void kernel_launch(void* const* d_in, const int* in_sizes, int n_in,
                              void* d_out, int out_size) {
    const float* x  = nullptr;  // 33554432
    const float* qw = nullptr;  // 786432
    const float* qb = nullptr;  // 1536
    const float* pw = nullptr;  // 262144
    const float* pb = nullptr;  // 512
    const float* bt = nullptr;  // 3600
    const int*   ri = nullptr;  // 4096
    for (int i = 0; i < n_in; i++) {
        switch (in_sizes[i]) {
            case 33554432: x  = (const float*)d_in[i]; break;
            case 786432:   qw = (const float*)d_in[i]; break;
            case 1536:     qb = (const float*)d_in[i]; break;
            case 262144:   pw = (const float*)d_in[i]; break;
            case 512:      pb = (const float*)d_in[i]; break;
            case 3600:     bt = (const float*)d_in[i]; break;
            case 4096:     ri = (const int*)d_in[i];   break;
            default: break;
        }
    }
    float* out = (float*)d_out;

    cudaFuncSetAttribute(k_gemm<true>, cudaFuncAttributeMaxDynamicSharedMemorySize,
                         SMEM_GEMM_BYTES);
    cudaFuncSetAttribute(k_gemm<false>, cudaFuncAttributeMaxDynamicSharedMemorySize,
                         SMEM_GEMM_BYTES);

    k_pre<<<4224, 1024>>>(x, qw, pw);
    k_bias_pre<<<dim3(4, 16), 256>>>(bt, ri);
    k_gemm<true><<<dim3(12, 512), 128, SMEM_GEMM_BYTES>>>(qb, nullptr);
    k_attn<<<dim3(1024, 16), 128>>>();
    k_gemm<false><<<dim3(4, 512), 128, SMEM_GEMM_BYTES>>>(pb, out);
}